// round 2
// baseline (speedup 1.0000x reference)
#include <cuda_runtime.h>

// ---------------------------------------------------------------------------
// Scratch (device globals: no allocations allowed in kernel_launch)
// ---------------------------------------------------------------------------
// Q/K/V each [B,T,C] = 2*2048*1024 floats = 16MB; yt = attention output
// already transposed to [B,T,H,hd] = [B,T,C].
__device__ float g_q [2u * 2048u * 1024u];
__device__ float g_k [2u * 2048u * 1024u];
__device__ float g_v [2u * 2048u * 1024u];
__device__ float g_yt[2u * 2048u * 1024u];

// ---------------------------------------------------------------------------
// Generic SGEMM: C = A[M,K] @ B[K,N] + bias[N]
// Output is routed to one of up to 3 buffers of width 1024 columns each
// (column block n/1024 selects the buffer; used to split QKV).
// BM=BN=128, BK=16, 256 threads, 8x8 microtile per thread.
// ---------------------------------------------------------------------------
__global__ __launch_bounds__(256) void gemm_bias_kernel(
    const float* __restrict__ A, const float* __restrict__ B,
    const float* __restrict__ bias,
    float* __restrict__ out0, float* __restrict__ out1, float* __restrict__ out2,
    int M, int N, int K)
{
    __shared__ float As[128 * 16];   // [row][k]
    __shared__ float Bs[16 * 128];   // [k][col]

    const int tid = threadIdx.x;
    const int tx = tid & 15;
    const int ty = tid >> 4;
    const int m0 = blockIdx.y * 128;
    const int n0 = blockIdx.x * 128;

    float acc[8][8];
#pragma unroll
    for (int i = 0; i < 8; ++i)
#pragma unroll
        for (int j = 0; j < 8; ++j) acc[i][j] = 0.0f;

    for (int k0 = 0; k0 < K; k0 += 16) {
        // Load A tile: 128 rows x 16 k = 512 float4
#pragma unroll
        for (int t = 0; t < 2; ++t) {
            int f = tid + t * 256;
            int r  = f >> 2;
            int c4 = (f & 3) << 2;
            float4 v = *(const float4*)(A + (size_t)(m0 + r) * K + k0 + c4);
            *(float4*)(As + r * 16 + c4) = v;
        }
        // Load B tile: 16 k x 128 cols = 512 float4
#pragma unroll
        for (int t = 0; t < 2; ++t) {
            int f = tid + t * 256;
            int r  = f >> 5;
            int c4 = (f & 31) << 2;
            float4 v = *(const float4*)(B + (size_t)(k0 + r) * N + n0 + c4);
            *(float4*)(Bs + r * 128 + c4) = v;
        }
        __syncthreads();

#pragma unroll
        for (int kk = 0; kk < 16; ++kk) {
            float a[8];
#pragma unroll
            for (int i = 0; i < 4; ++i) {
                a[i]     = As[(ty * 4 + i) * 16 + kk];
                a[4 + i] = As[(64 + ty * 4 + i) * 16 + kk];
            }
            float4 b0 = *(const float4*)(Bs + kk * 128 + tx * 4);
            float4 b1 = *(const float4*)(Bs + kk * 128 + 64 + tx * 4);
            float bb[8] = {b0.x, b0.y, b0.z, b0.w, b1.x, b1.y, b1.z, b1.w};
#pragma unroll
            for (int i = 0; i < 8; ++i)
#pragma unroll
                for (int j = 0; j < 8; ++j)
                    acc[i][j] = fmaf(a[i], bb[j], acc[i][j]);
        }
        __syncthreads();
    }

    // Epilogue: bias + store. Whole 128-col tile lives in one 1024-col buffer.
    float* outp = (n0 < 1024) ? out0 : ((n0 < 2048) ? out1 : out2);
    const int nc = n0 & 1023;

#pragma unroll
    for (int jg = 0; jg < 2; ++jg) {
        const int coll = nc + jg * 64 + tx * 4;       // col in dest buffer
        const int colg = n0 + jg * 64 + tx * 4;       // col for bias
        float4 bv = *(const float4*)(bias + colg);
#pragma unroll
        for (int ig = 0; ig < 2; ++ig) {
#pragma unroll
            for (int i = 0; i < 4; ++i) {
                int row = m0 + ig * 64 + ty * 4 + i;
                int ai = ig * 4 + i;
                float4 v;
                v.x = acc[ai][jg * 4 + 0] + bv.x;
                v.y = acc[ai][jg * 4 + 1] + bv.y;
                v.z = acc[ai][jg * 4 + 2] + bv.z;
                v.w = acc[ai][jg * 4 + 3] + bv.w;
                *(float4*)(outp + (size_t)row * 1024 + coll) = v;
            }
        }
    }
}

// ---------------------------------------------------------------------------
// Flash attention (causal), fp32, per-head seq = 2048, hd = 64.
// Grid: (32 q-tiles, 32 bh). 256 threads; Br=Bc=64; 4x4 S microtile.
// Q pre-scaled by 1/sqrt(64)=0.125. Output written transposed to [B,T,H,hd].
// K smem buffer is reused for P after S is computed.
// ---------------------------------------------------------------------------
#define FA_PAD 65

__global__ __launch_bounds__(256) void flash_kernel(
    const float* __restrict__ Qg, const float* __restrict__ Kg,
    const float* __restrict__ Vg, float* __restrict__ yt)
{
    extern __shared__ float sm[];
    float* Qs  = sm;                   // [64][FA_PAD]
    float* KPs = sm + 64 * FA_PAD;     // K tile, then P
    float* Vs  = sm + 2 * 64 * FA_PAD; // [64][FA_PAD]

    const int qt  = blockIdx.x;        // 0..31
    const int bh  = blockIdx.y;        // 0..31
    const int tid = threadIdx.x;
    const int tx  = tid & 15;
    const int ty  = tid >> 4;
    const int r0  = ty * 4;
    const int c0  = tx * 4;

    const size_t head_off = (size_t)bh * 131072u;  // 2048*64
    const float* qb = Qg + head_off + (size_t)qt * 4096u;

    // Load Q tile (scaled)
    for (int f = tid; f < 1024; f += 256) {
        int r  = f >> 4;
        int c4 = (f & 15) << 2;
        float4 t = *(const float4*)(qb + r * 64 + c4);
        float* dst = Qs + r * FA_PAD + c4;
        dst[0] = t.x * 0.125f; dst[1] = t.y * 0.125f;
        dst[2] = t.z * 0.125f; dst[3] = t.w * 0.125f;
    }

    float m[4], l[4], o[4][4];
#pragma unroll
    for (int i = 0; i < 4; ++i) {
        m[i] = -1e30f; l[i] = 0.0f;
#pragma unroll
        for (int j = 0; j < 4; ++j) o[i][j] = 0.0f;
    }

    for (int kt = 0; kt <= qt; ++kt) {
        __syncthreads();   // protect KPs/Vs reuse across iterations (and Q load)
        const float* kb = Kg + head_off + (size_t)kt * 4096u;
        const float* vb = Vg + head_off + (size_t)kt * 4096u;
        for (int f = tid; f < 1024; f += 256) {
            int r  = f >> 4;
            int c4 = (f & 15) << 2;
            float4 tk = *(const float4*)(kb + r * 64 + c4);
            float4 tv = *(const float4*)(vb + r * 64 + c4);
            float* dk = KPs + r * FA_PAD + c4;
            dk[0] = tk.x; dk[1] = tk.y; dk[2] = tk.z; dk[3] = tk.w;
            float* dv = Vs + r * FA_PAD + c4;
            dv[0] = tv.x; dv[1] = tv.y; dv[2] = tv.z; dv[3] = tv.w;
        }
        __syncthreads();

        // S = Q K^T  (4x4 per thread)
        float s[4][4];
#pragma unroll
        for (int i = 0; i < 4; ++i)
#pragma unroll
            for (int j = 0; j < 4; ++j) s[i][j] = 0.0f;

#pragma unroll 8
        for (int d = 0; d < 64; ++d) {
            float qa[4], kv[4];
#pragma unroll
            for (int i = 0; i < 4; ++i) qa[i] = Qs[(r0 + i) * FA_PAD + d];
#pragma unroll
            for (int j = 0; j < 4; ++j) kv[j] = KPs[(c0 + j) * FA_PAD + d];
#pragma unroll
            for (int i = 0; i < 4; ++i)
#pragma unroll
                for (int j = 0; j < 4; ++j)
                    s[i][j] = fmaf(qa[i], kv[j], s[i][j]);
        }

        // Causal mask on diagonal tile
        if (kt == qt) {
#pragma unroll
            for (int i = 0; i < 4; ++i)
#pragma unroll
                for (int j = 0; j < 4; ++j)
                    if (c0 + j > r0 + i) s[i][j] = -1e30f;
        }

        // Online softmax update (row reductions across tx via 16-lane shuffles)
        float alpha[4];
#pragma unroll
        for (int i = 0; i < 4; ++i) {
            float mx = fmaxf(fmaxf(s[i][0], s[i][1]), fmaxf(s[i][2], s[i][3]));
#pragma unroll
            for (int off = 8; off > 0; off >>= 1)
                mx = fmaxf(mx, __shfl_xor_sync(0xffffffffu, mx, off));
            float mn = fmaxf(m[i], mx);
            alpha[i] = __expf(m[i] - mn);
            m[i] = mn;

            float sum = 0.0f;
#pragma unroll
            for (int j = 0; j < 4; ++j) {
                s[i][j] = __expf(s[i][j] - mn);
                sum += s[i][j];
            }
#pragma unroll
            for (int off = 8; off > 0; off >>= 1)
                sum += __shfl_xor_sync(0xffffffffu, sum, off);
            l[i] = l[i] * alpha[i] + sum;
#pragma unroll
            for (int j = 0; j < 4; ++j) o[i][j] *= alpha[i];
        }

        __syncthreads();   // all reads of K done before overwriting with P
#pragma unroll
        for (int i = 0; i < 4; ++i)
#pragma unroll
            for (int j = 0; j < 4; ++j)
                KPs[(r0 + i) * FA_PAD + c0 + j] = s[i][j];
        __syncthreads();

        // O += P @ V   (O dims for this thread: c0..c0+3)
#pragma unroll 8
        for (int c = 0; c < 64; ++c) {
            float p[4], vv[4];
#pragma unroll
            for (int i = 0; i < 4; ++i) p[i] = KPs[(r0 + i) * FA_PAD + c];
#pragma unroll
            for (int j = 0; j < 4; ++j) vv[j] = Vs[c * FA_PAD + c0 + j];
#pragma unroll
            for (int i = 0; i < 4; ++i)
#pragma unroll
                for (int j = 0; j < 4; ++j)
                    o[i][j] = fmaf(p[i], vv[j], o[i][j]);
        }
    }

    // Epilogue: normalize and write to [B, T, H, hd] layout
    const int b = bh >> 4;
    const int h = bh & 15;
#pragma unroll
    for (int i = 0; i < 4; ++i) {
        int tq = qt * 64 + r0 + i;     // t' within head
        float inv = 1.0f / l[i];
        float4 v;
        v.x = o[i][0] * inv; v.y = o[i][1] * inv;
        v.z = o[i][2] * inv; v.w = o[i][3] * inv;
        *(float4*)(yt + ((size_t)(b * 2048 + tq)) * 1024u + h * 64 + c0) = v;
    }
}

// ---------------------------------------------------------------------------
// Launch
// ---------------------------------------------------------------------------
extern "C" void kernel_launch(void* const* d_in, const int* in_sizes, int n_in,
                              void* d_out, int out_size)
{
    const float* x     = (const float*)d_in[0];
    const float* Wqkv  = (const float*)d_in[1];
    const float* bqkv  = (const float*)d_in[2];
    const float* Wproj = (const float*)d_in[3];
    const float* bproj = (const float*)d_in[4];
    float* out = (float*)d_out;

    float *q, *k, *v, *yt;
    cudaGetSymbolAddress((void**)&q,  g_q);
    cudaGetSymbolAddress((void**)&k,  g_k);
    cudaGetSymbolAddress((void**)&v,  g_v);
    cudaGetSymbolAddress((void**)&yt, g_yt);

    const int M = 2 * 2048;   // 4096
    const int C = 1024;

    // 1) QKV projection: x @ Wqkv + bqkv -> q/k/v (split by 1024-col block)
    {
        dim3 grid(3 * C / 128, M / 128);   // (24, 32)
        gemm_bias_kernel<<<grid, 256>>>(x, Wqkv, bqkv, q, k, v, M, 3 * C, C);
    }

    // 2) Flash attention (causal) -> yt in [B,T,H,hd] layout
    {
        const int smem = 3 * 64 * FA_PAD * (int)sizeof(float);   // 49920 B
        cudaFuncSetAttribute(flash_kernel,
                             cudaFuncAttributeMaxDynamicSharedMemorySize, smem);
        dim3 grid(2048 / 64, 32);          // (32 q-tiles, 32 bh)
        flash_kernel<<<grid, 256, smem>>>(q, k, v, yt);
    }

    // 3) Output projection: yt @ Wproj + bproj -> out
    {
        dim3 grid(C / 128, M / 128);       // (8, 32)
        gemm_bias_kernel<<<grid, 256>>>(yt, Wproj, bproj, out, out, out, M, C, C);
    }
}

// round 3
// speedup vs baseline: 1.3994x; 1.3994x over previous
#include <cuda_runtime.h>
#include <mma.h>

using namespace nvcuda;
namespace wm = nvcuda::wmma;

// ---------------------------------------------------------------------------
// Scratch (device globals)
// ---------------------------------------------------------------------------
__device__ float g_q [2u * 2048u * 1024u];
__device__ float g_k [2u * 2048u * 1024u];
__device__ float g_v [2u * 2048u * 1024u];
__device__ float g_yt[2u * 2048u * 1024u];

// ---------------------------------------------------------------------------
// TF32 WMMA GEMM: C = A[M,K] @ B[K,N] + bias[N]
// BM=128, BN=128, BK=32, 256 threads (8 warps, 4x2), warp tile 32x64.
// Output routed into one of 3 buffers of width 1024 (QKV split).
// ---------------------------------------------------------------------------
__global__ __launch_bounds__(256) void gemm_tf32_kernel(
    const float* __restrict__ A, const float* __restrict__ B,
    const float* __restrict__ bias,
    float* __restrict__ out0, float* __restrict__ out1, float* __restrict__ out2,
    int M, int N, int K)
{
    __shared__ float As[128][40];     // [m][k], tf32-rounded
    __shared__ float Bs[32][136];     // [k][n], tf32-rounded
    __shared__ float Brep[16][136];   // bias replicated across 16 rows

    const int tid  = threadIdx.x;
    const int wid  = tid >> 5;
    const int wm   = wid & 3;         // 4 warps over M: 32 rows each
    const int wn   = wid >> 2;        // 2 warps over N: 64 cols each
    const int m0   = blockIdx.y * 128;
    const int n0   = blockIdx.x * 128;

    // Fill bias replication tile
    for (int i = tid; i < 16 * 128; i += 256) {
        int r = i >> 7, c = i & 127;
        Brep[r][c] = bias[n0 + c];
    }
    __syncthreads();

    wm::fragment<wm::accumulator, 16, 16, 8, float> acc[2][4];
#pragma unroll
    for (int mi = 0; mi < 2; ++mi)
#pragma unroll
        for (int ni = 0; ni < 4; ++ni)
            wm::load_matrix_sync(acc[mi][ni], &Brep[0][wn * 64 + ni * 16], 136,
                                 wm::mem_row_major);
    __syncthreads();

    for (int k0 = 0; k0 < K; k0 += 32) {
        // A tile: 128x32 = 1024 float4
#pragma unroll
        for (int t = 0; t < 4; ++t) {
            int f = tid + t * 256;
            int r = f >> 3, c4 = (f & 7) << 2;
            float4 v = *(const float4*)(A + (size_t)(m0 + r) * K + k0 + c4);
            As[r][c4 + 0] = wm::__float_to_tf32(v.x);
            As[r][c4 + 1] = wm::__float_to_tf32(v.y);
            As[r][c4 + 2] = wm::__float_to_tf32(v.z);
            As[r][c4 + 3] = wm::__float_to_tf32(v.w);
        }
        // B tile: 32x128 = 1024 float4
#pragma unroll
        for (int t = 0; t < 4; ++t) {
            int f = tid + t * 256;
            int r = f >> 5, c4 = (f & 31) << 2;
            float4 v = *(const float4*)(B + (size_t)(k0 + r) * N + n0 + c4);
            Bs[r][c4 + 0] = wm::__float_to_tf32(v.x);
            Bs[r][c4 + 1] = wm::__float_to_tf32(v.y);
            Bs[r][c4 + 2] = wm::__float_to_tf32(v.z);
            Bs[r][c4 + 3] = wm::__float_to_tf32(v.w);
        }
        __syncthreads();

#pragma unroll
        for (int ks = 0; ks < 4; ++ks) {
            wm::fragment<wm::matrix_a, 16, 16, 8, wm::precision::tf32, wm::row_major> af[2];
            wm::fragment<wm::matrix_b, 16, 16, 8, wm::precision::tf32, wm::row_major> bf[4];
#pragma unroll
            for (int mi = 0; mi < 2; ++mi)
                wm::load_matrix_sync(af[mi], &As[wm * 32 + mi * 16][ks * 8], 40);
#pragma unroll
            for (int ni = 0; ni < 4; ++ni)
                wm::load_matrix_sync(bf[ni], &Bs[ks * 8][wn * 64 + ni * 16], 136);
#pragma unroll
            for (int mi = 0; mi < 2; ++mi)
#pragma unroll
                for (int ni = 0; ni < 4; ++ni)
                    wm::mma_sync(acc[mi][ni], af[mi], bf[ni], acc[mi][ni]);
        }
        __syncthreads();
    }

    // Epilogue: route to one of 3 buffers of width 1024
    float* outp = (n0 < 1024) ? out0 : ((n0 < 2048) ? out1 : out2);
    const int nc = n0 & 1023;
#pragma unroll
    for (int mi = 0; mi < 2; ++mi)
#pragma unroll
        for (int ni = 0; ni < 4; ++ni) {
            float* p = outp + (size_t)(m0 + wm * 32 + mi * 16) * 1024
                            + nc + wn * 64 + ni * 16;
            wm::store_matrix_sync(p, acc[mi][ni], 1024, wm::mem_row_major);
        }
}

// ---------------------------------------------------------------------------
// Flash attention (causal) with TF32 WMMA for QK^T and PV.
// Br=Bc=64, hd=64. 256 threads (8 warps). Each thread owns ONE S/O row
// quarter (row = tid>>2, 16 cols) for the scalar softmax / O update.
// Output written transposed to [B, T, H, hd].
// ---------------------------------------------------------------------------
#define FLD 72   // padded leading dim for 64-wide tiles

__global__ __launch_bounds__(256) void flash_tf32_kernel(
    const float* __restrict__ Qg, const float* __restrict__ Kg,
    const float* __restrict__ Vg, float* __restrict__ yt)
{
    extern __shared__ float sm[];
    float* Qs    = sm;                  // [64][FLD] tf32, pre-scaled
    float* Ks    = Qs    + 64 * FLD;    // [64][FLD] tf32
    float* Vs    = Ks    + 64 * FLD;    // [64][FLD] tf32
    float* Ss    = Vs    + 64 * FLD;    // [64][FLD] S then P(tf32)
    float* Oacc  = Ss    + 64 * FLD;    // [64][FLD] fp32 running O
    float* Opart = Oacc  + 64 * FLD;    // [64][FLD] fp32 P@V partial
    float* alphaS= Opart + 64 * FLD;    // [64]

    const int qt  = blockIdx.x;
    const int bh  = blockIdx.y;
    const int tid = threadIdx.x;
    const int wid = tid >> 5;
    const int wm  = wid & 3;            // warp row-tile (16 rows)
    const int wn  = wid >> 2;           // warp col-half (32 cols)

    const int r   = tid >> 2;           // softmax row owned (0..63)
    const int qq  = tid & 3;            // column quarter (16 cols)

    const size_t head_off = (size_t)bh * 131072u;
    const float* qb = Qg + head_off + (size_t)qt * 4096u;

    // Load Q tile (scaled by 1/8, tf32-rounded); zero Oacc
    for (int f = tid; f < 1024; f += 256) {
        int rr = f >> 4, c4 = (f & 15) << 2;
        float4 t = *(const float4*)(qb + rr * 64 + c4);
        float* dst = Qs + rr * FLD + c4;
        dst[0] = wm::__float_to_tf32(t.x * 0.125f);
        dst[1] = wm::__float_to_tf32(t.y * 0.125f);
        dst[2] = wm::__float_to_tf32(t.z * 0.125f);
        dst[3] = wm::__float_to_tf32(t.w * 0.125f);
        float4 z = {0.f, 0.f, 0.f, 0.f};
        *(float4*)(Oacc + rr * FLD + c4) = z;
    }

    float mrow = -1e30f, lrow = 0.0f;

    for (int kt = 0; kt <= qt; ++kt) {
        __syncthreads();
        // Load K/V tiles (tf32-rounded)
        const float* kb = Kg + head_off + (size_t)kt * 4096u;
        const float* vb = Vg + head_off + (size_t)kt * 4096u;
        for (int f = tid; f < 1024; f += 256) {
            int rr = f >> 4, c4 = (f & 15) << 2;
            float4 tk = *(const float4*)(kb + rr * 64 + c4);
            float4 tv = *(const float4*)(vb + rr * 64 + c4);
            float* dk = Ks + rr * FLD + c4;
            dk[0] = wm::__float_to_tf32(tk.x); dk[1] = wm::__float_to_tf32(tk.y);
            dk[2] = wm::__float_to_tf32(tk.z); dk[3] = wm::__float_to_tf32(tk.w);
            float* dv = Vs + rr * FLD + c4;
            dv[0] = wm::__float_to_tf32(tv.x); dv[1] = wm::__float_to_tf32(tv.y);
            dv[2] = wm::__float_to_tf32(tv.z); dv[3] = wm::__float_to_tf32(tv.w);
        }
        __syncthreads();

        // ---- S = Q @ K^T (K as col-major B operand) ----
        {
            wm::fragment<wm::accumulator, 16, 16, 8, float> sacc[2];
#pragma unroll
            for (int ni = 0; ni < 2; ++ni) wm::fill_fragment(sacc[ni], 0.0f);
#pragma unroll
            for (int ks = 0; ks < 8; ++ks) {
                wm::fragment<wm::matrix_a, 16, 16, 8, wm::precision::tf32, wm::row_major> af;
                wm::fragment<wm::matrix_b, 16, 16, 8, wm::precision::tf32, wm::col_major> bf[2];
                wm::load_matrix_sync(af, Qs + (wm * 16) * FLD + ks * 8, FLD);
#pragma unroll
                for (int ni = 0; ni < 2; ++ni)
                    wm::load_matrix_sync(bf[ni], Ks + (wn * 32 + ni * 16) * FLD + ks * 8, FLD);
#pragma unroll
                for (int ni = 0; ni < 2; ++ni)
                    wm::mma_sync(sacc[ni], af, bf[ni], sacc[ni]);
            }
#pragma unroll
            for (int ni = 0; ni < 2; ++ni)
                wm::store_matrix_sync(Ss + (wm * 16) * FLD + wn * 32 + ni * 16,
                                      sacc[ni], FLD, wm::mem_row_major);
        }
        __syncthreads();

        // ---- Online softmax (scalar): row r, cols qq*16..qq*16+15 ----
        {
            float s[16];
            float* srow = Ss + r * FLD + qq * 16;
            const bool diag = (kt == qt);
#pragma unroll
            for (int j = 0; j < 16; ++j) {
                float v = srow[j];
                if (diag && (qq * 16 + j > r)) v = -1e30f;
                s[j] = v;
            }
            float mx = -1e30f;
#pragma unroll
            for (int j = 0; j < 16; ++j) mx = fmaxf(mx, s[j]);
            mx = fmaxf(mx, __shfl_xor_sync(0xffffffffu, mx, 1));
            mx = fmaxf(mx, __shfl_xor_sync(0xffffffffu, mx, 2));

            float mn = fmaxf(mrow, mx);
            float alpha = __expf(mrow - mn);
            mrow = mn;

            float sum = 0.0f;
#pragma unroll
            for (int j = 0; j < 16; ++j) {
                float p = __expf(s[j] - mn);
                sum += p;
                srow[j] = wm::__float_to_tf32(p);   // P (tf32) back into Ss
            }
            sum += __shfl_xor_sync(0xffffffffu, sum, 1);
            sum += __shfl_xor_sync(0xffffffffu, sum, 2);
            lrow = lrow * alpha + sum;
            if (qq == 0) alphaS[r] = alpha;
        }
        __syncthreads();

        // ---- Opart = P @ V ----
        {
            wm::fragment<wm::accumulator, 16, 16, 8, float> oacc[2];
#pragma unroll
            for (int ni = 0; ni < 2; ++ni) wm::fill_fragment(oacc[ni], 0.0f);
#pragma unroll
            for (int ks = 0; ks < 8; ++ks) {
                wm::fragment<wm::matrix_a, 16, 16, 8, wm::precision::tf32, wm::row_major> af;
                wm::fragment<wm::matrix_b, 16, 16, 8, wm::precision::tf32, wm::row_major> bf[2];
                wm::load_matrix_sync(af, Ss + (wm * 16) * FLD + ks * 8, FLD);
#pragma unroll
                for (int ni = 0; ni < 2; ++ni)
                    wm::load_matrix_sync(bf[ni], Vs + (ks * 8) * FLD + wn * 32 + ni * 16, FLD);
#pragma unroll
                for (int ni = 0; ni < 2; ++ni)
                    wm::mma_sync(oacc[ni], af, bf[ni], oacc[ni]);
            }
#pragma unroll
            for (int ni = 0; ni < 2; ++ni)
                wm::store_matrix_sync(Opart + (wm * 16) * FLD + wn * 32 + ni * 16,
                                      oacc[ni], FLD, wm::mem_row_major);
        }
        __syncthreads();

        // ---- O update: Oacc = Oacc * alpha + Opart ----
        {
            float alpha = alphaS[r];
            float* oa = Oacc  + r * FLD + qq * 16;
            float* op = Opart + r * FLD + qq * 16;
#pragma unroll
            for (int j4 = 0; j4 < 4; ++j4) {
                float4 a = *(float4*)(oa + j4 * 4);
                float4 p = *(float4*)(op + j4 * 4);
                a.x = a.x * alpha + p.x; a.y = a.y * alpha + p.y;
                a.z = a.z * alpha + p.z; a.w = a.w * alpha + p.w;
                *(float4*)(oa + j4 * 4) = a;
            }
        }
    }
    __syncthreads();

    // ---- Epilogue: normalize, write to [B, T, H, hd] ----
    {
        const int b = bh >> 4;
        const int h = bh & 15;
        const float inv = 1.0f / lrow;
        const int tq = qt * 64 + r;
        float* oa = Oacc + r * FLD + qq * 16;
        float* dst = yt + ((size_t)(b * 2048 + tq)) * 1024u + h * 64 + qq * 16;
#pragma unroll
        for (int j4 = 0; j4 < 4; ++j4) {
            float4 a = *(float4*)(oa + j4 * 4);
            a.x *= inv; a.y *= inv; a.z *= inv; a.w *= inv;
            *(float4*)(dst + j4 * 4) = a;
        }
    }
}

// ---------------------------------------------------------------------------
// Launch
// ---------------------------------------------------------------------------
extern "C" void kernel_launch(void* const* d_in, const int* in_sizes, int n_in,
                              void* d_out, int out_size)
{
    const float* x     = (const float*)d_in[0];
    const float* Wqkv  = (const float*)d_in[1];
    const float* bqkv  = (const float*)d_in[2];
    const float* Wproj = (const float*)d_in[3];
    const float* bproj = (const float*)d_in[4];
    float* out = (float*)d_out;

    float *q, *k, *v, *yt;
    cudaGetSymbolAddress((void**)&q,  g_q);
    cudaGetSymbolAddress((void**)&k,  g_k);
    cudaGetSymbolAddress((void**)&v,  g_v);
    cudaGetSymbolAddress((void**)&yt, g_yt);

    const int M = 2 * 2048;   // 4096
    const int C = 1024;

    // 1) QKV projection
    {
        dim3 grid(3 * C / 128, M / 128);   // (24, 32)
        gemm_tf32_kernel<<<grid, 256>>>(x, Wqkv, bqkv, q, k, v, M, 3 * C, C);
    }

    // 2) Flash attention (causal)
    {
        const int smem = (6 * 64 * FLD + 64) * (int)sizeof(float);  // 110848 B
        cudaFuncSetAttribute(flash_tf32_kernel,
                             cudaFuncAttributeMaxDynamicSharedMemorySize, smem);
        dim3 grid(2048 / 64, 32);
        flash_tf32_kernel<<<grid, 256, smem>>>(q, k, v, yt);
    }

    // 3) Output projection
    {
        dim3 grid(C / 128, M / 128);       // (8, 32)
        gemm_tf32_kernel<<<grid, 256>>>(yt, Wproj, bproj, out, out, out, M, C, C);
    }
}